// round 4
// baseline (speedup 1.0000x reference)
#include <cuda_runtime.h>
#include <cuda_bf16.h>
#include <cstdint>

// Problem constants
#define NXg 512
#define NYg 512
#define NSENS 128
#define NT 2048
#define NPIX (NXg * NYg)

#define WWIN 60          // staged window entries per (tile,sensor); true span <= 56
#define WSTR 3           // float4 slots per entry (48B stride => period-8 bank rotation)

// Scratch: sensor data transposed to [s][t][8 channels] as 2x float4 per (s,t).
// 128 * 2048 * 8 floats = 8 MB (L2-resident).
__device__ float4 g_scratch[NSENS * NT * 2];

// ---------------------------------------------------------------------------
// Prep kernel: transpose sensor_data [B=4][C=2][S=128][T=2048] -> [S][T][bc=8]
// ---------------------------------------------------------------------------
__global__ __launch_bounds__(256) void das_transpose_kernel(
    const float* __restrict__ sd)
{
    int idx = blockIdx.x * blockDim.x + threadIdx.x;   // 0 .. 128*2048-1
    if (idx >= NSENS * NT) return;
    int s = idx >> 11;
    int t = idx & (NT - 1);

    const int bcStride = NSENS * NT;
    const float* base = sd + s * NT + t;

    float4 v0, v1;
    v0.x = base[0 * bcStride];
    v0.y = base[1 * bcStride];
    v0.z = base[2 * bcStride];
    v0.w = base[3 * bcStride];
    v1.x = base[4 * bcStride];
    v1.y = base[5 * bcStride];
    v1.z = base[6 * bcStride];
    v1.w = base[7 * bcStride];

    g_scratch[idx * 2 + 0] = v0;
    g_scratch[idx * 2 + 1] = v1;
}

// ---------------------------------------------------------------------------
// Main DAS kernel: 16x16 pixel tile per block, smem-staged per-sensor windows.
// ---------------------------------------------------------------------------
__global__ __launch_bounds__(256) void das_main_kernel(
    const int* __restrict__ sensor_xy,   // [128][2] int32
    float* __restrict__ out)             // [8][NPIX]
{
    __shared__ float2 sxy[NSENS];
    __shared__ int    stmin[NSENS];
    __shared__ float4 sbuf[2][WWIN * WSTR];   // 2 x 2880B double buffer

    const int tx = threadIdx.x, ty = threadIdx.y;
    const int tid = ty * 16 + tx;
    const int iy0 = blockIdx.x * 16;
    const int ix0 = blockIdx.y * 16;

    // XLA chain: dis/VS/DT -> dis * fl(fl(1/VS)*fl(1/DT)); bit-exact (R3).
    const float K = (1.0f / 1550.0f) * (1.0f / 2.5e-8f);

    // Per-sensor window base: t at the tile point nearest the sensor, computed
    // through the SAME monotone RN chain => t_min <= t(pixel) exactly in fp32.
    if (tid < NSENS) {
        int2 xy = ((const int2*)sensor_xy)[tid];
        float cx = (float)xy.x, cy = (float)xy.y;
        sxy[tid] = make_float2(cx, cy);
        float px = fminf(fmaxf(cx, (float)ix0), (float)(ix0 + 15));
        float py = fminf(fmaxf(cy, (float)iy0), (float)(iy0 + 15));
        float dx = __fmul_rn(cx - px, 1e-4f);
        float dy = __fmul_rn(cy - py, 1e-4f);
        float dis = __fsqrt_rn(__fadd_rn(__fmul_rn(dx, dx), __fmul_rn(dy, dy)));
        stmin[tid] = (int)__fmul_rn(dis, K);
        // max t overall = 2.58*511*sqrt2 ~ 1865, so t_min + 59 < 2048: staging
        // never reads out of bounds.
    }
    __syncthreads();

    // Stage sensor 0 into buffer 0 (threads 0..119, one float4 each).
    if (tid < 2 * WWIN) {
        int e = tid >> 1, h = tid & 1;
        sbuf[0][e * WSTR + h] =
            g_scratch[(((unsigned)stmin[0] + e) << 1) + h];
    }

    const float fix = (float)(ix0 + ty);
    const float fiy = (float)(iy0 + tx);

    float4 a0 = make_float4(0.f, 0.f, 0.f, 0.f);
    float4 a1 = make_float4(0.f, 0.f, 0.f, 0.f);

    #pragma unroll 1
    for (int s = 0; s < NSENS; ++s) {
        __syncthreads();   // publishes sbuf[s&1]; retires gathers on sbuf[(s+1)&1]
        const int cur = s & 1;

        // Prefetch next sensor's window into the other buffer.
        if (s + 1 < NSENS && tid < 2 * WWIN) {
            int e = tid >> 1, h = tid & 1;
            sbuf[cur ^ 1][e * WSTR + h] =
                g_scratch[(((((unsigned)(s + 1)) << 11) + (unsigned)stmin[s + 1] + e) << 1) + h];
        }

        // Delay index (bit-exact chain from R3 — do not modify).
        float2 c = sxy[s];
        float dx = __fmul_rn(c.x - fix, 1e-4f);
        float dy = __fmul_rn(c.y - fiy, 1e-4f);
        float dis = __fsqrt_rn(__fadd_rn(__fmul_rn(dx, dx), __fmul_rn(dy, dy)));
        int t = (int)__fmul_rn(dis, K);
        int tloc = t - stmin[s];

        float4 v0 = sbuf[cur][tloc * WSTR + 0];
        float4 v1 = sbuf[cur][tloc * WSTR + 1];
        a0.x += v0.x; a0.y += v0.y; a0.z += v0.z; a0.w += v0.w;
        a1.x += v1.x; a1.y += v1.y; a1.z += v1.z; a1.w += v1.w;
    }

    const int p = (ix0 + ty) * NYg + (iy0 + tx);
    out[0 * NPIX + p] = a0.x;
    out[1 * NPIX + p] = a0.y;
    out[2 * NPIX + p] = a0.z;
    out[3 * NPIX + p] = a0.w;
    out[4 * NPIX + p] = a1.x;
    out[5 * NPIX + p] = a1.y;
    out[6 * NPIX + p] = a1.z;
    out[7 * NPIX + p] = a1.w;
}

// ---------------------------------------------------------------------------
// Entry point
// ---------------------------------------------------------------------------
extern "C" void kernel_launch(void* const* d_in, const int* in_sizes, int n_in,
                              void* d_out, int out_size)
{
    const float* sensor_data = (const float*)d_in[0];   // (4,2,128,2048) f32
    const int*   sensor_xy   = (const int*)d_in[1];     // (128,2) i32
    float*       out         = (float*)d_out;           // (4,2,512,512) f32

    das_transpose_kernel<<<(NSENS * NT + 255) / 256, 256>>>(sensor_data);

    dim3 block(16, 16);
    dim3 grid(NYg / 16, NXg / 16);
    das_main_kernel<<<grid, block>>>(sensor_xy, out);
}

// round 5
// speedup vs baseline: 1.4510x; 1.4510x over previous
#include <cuda_runtime.h>
#include <cuda_bf16.h>
#include <cstdint>

// Problem constants
#define NXg 512
#define NYg 512
#define NSENS 128
#define NT 2048
#define NPIX (NXg * NYg)

// Two half-channel scratch arrays: [s][t][4ch] as one float4 per (s,t).
// 4 MB each; a 128B line holds 8 consecutive t entries -> low line overfetch.
__device__ float4 g_scratchA[NSENS * NT];   // channels 0..3 (b0c0,b0c1,b1c0,b1c1)
__device__ float4 g_scratchB[NSENS * NT];   // channels 4..7

// ---------------------------------------------------------------------------
// Prep kernel: transpose sensor_data [B=4][C=2][S=128][T=2048] -> 2x [S][T][4]
// ---------------------------------------------------------------------------
__global__ __launch_bounds__(256) void das_transpose_kernel(
    const float* __restrict__ sd)
{
    int idx = blockIdx.x * blockDim.x + threadIdx.x;   // 0 .. 128*2048-1
    if (idx >= NSENS * NT) return;
    int s = idx >> 11;
    int t = idx & (NT - 1);

    const int bcStride = NSENS * NT;
    const float* base = sd + s * NT + t;

    float4 v0, v1;
    v0.x = base[0 * bcStride];
    v0.y = base[1 * bcStride];
    v0.z = base[2 * bcStride];
    v0.w = base[3 * bcStride];
    v1.x = base[4 * bcStride];
    v1.y = base[5 * bcStride];
    v1.z = base[6 * bcStride];
    v1.w = base[7 * bcStride];

    g_scratchA[idx] = v0;
    g_scratchB[idx] = v1;
}

// ---------------------------------------------------------------------------
// Main DAS kernel: one thread per pixel, 128-sensor loop.
// 16x16 tile per block; each WARP covers a compact 8(iy) x 4(ix) patch to
// minimize the per-warp delay span (unique L1 lines per gather).
// ---------------------------------------------------------------------------
__global__ __launch_bounds__(256) void das_main_kernel(
    const int* __restrict__ sensor_xy,   // [128][2] int32
    float* __restrict__ out)             // [8][NPIX]
{
    __shared__ float2 sxy[NSENS];

    const int tid  = threadIdx.x;        // 0..255
    const int lane = tid & 31;
    const int w    = tid >> 5;           // 0..7

    if (tid < NSENS) {
        int2 xy = ((const int2*)sensor_xy)[tid];
        sxy[tid] = make_float2((float)xy.x, (float)xy.y);
    }
    __syncthreads();

    // Warp patch: 8 iy x 4 ix. Warps tile 2x4 over the 16x16 block tile.
    const int ly = lane & 7;             // iy offset within warp patch
    const int lx = lane >> 3;            // ix offset within warp patch (0..3)
    const int wy = w & 1;                // warp's iy block (0..1) * 8
    const int wx = w >> 1;               // warp's ix block (0..3) * 4

    const int iy = blockIdx.x * 16 + wy * 8 + ly;
    const int ix = blockIdx.y * 16 + wx * 4 + lx;

    const float fix = (float)ix;
    const float fiy = (float)iy;

    // XLA chain (bit-exact, validated R3): dis * fl(fl(1/VS)*fl(1/DT)).
    const float K = (1.0f / 1550.0f) * (1.0f / 2.5e-8f);

    float4 a0 = make_float4(0.f, 0.f, 0.f, 0.f);
    float4 a1 = make_float4(0.f, 0.f, 0.f, 0.f);

    #pragma unroll 4
    for (int s = 0; s < NSENS; ++s) {
        float2 c = sxy[s];
        float dx = __fmul_rn(c.x - fix, 1e-4f);
        float dy = __fmul_rn(c.y - fiy, 1e-4f);
        float r2 = __fadd_rn(__fmul_rn(dx, dx), __fmul_rn(dy, dy));
        float dis = __fsqrt_rn(r2);
        int t = (int)__fmul_rn(dis, K);

        unsigned off = ((unsigned)s << 11) + (unsigned)t;
        float4 v0 = __ldg(&g_scratchA[off]);
        float4 v1 = __ldg(&g_scratchB[off]);
        a0.x += v0.x; a0.y += v0.y; a0.z += v0.z; a0.w += v0.w;
        a1.x += v1.x; a1.y += v1.y; a1.z += v1.z; a1.w += v1.w;
    }

    const int p = ix * NYg + iy;
    out[0 * NPIX + p] = a0.x;
    out[1 * NPIX + p] = a0.y;
    out[2 * NPIX + p] = a0.z;
    out[3 * NPIX + p] = a0.w;
    out[4 * NPIX + p] = a1.x;
    out[5 * NPIX + p] = a1.y;
    out[6 * NPIX + p] = a1.z;
    out[7 * NPIX + p] = a1.w;
}

// ---------------------------------------------------------------------------
// Entry point
// ---------------------------------------------------------------------------
extern "C" void kernel_launch(void* const* d_in, const int* in_sizes, int n_in,
                              void* d_out, int out_size)
{
    const float* sensor_data = (const float*)d_in[0];   // (4,2,128,2048) f32
    const int*   sensor_xy   = (const int*)d_in[1];     // (128,2) i32
    float*       out         = (float*)d_out;           // (4,2,512,512) f32

    das_transpose_kernel<<<(NSENS * NT + 255) / 256, 256>>>(sensor_data);

    dim3 block(256);
    dim3 grid(NYg / 16, NXg / 16);
    das_main_kernel<<<grid, block>>>(sensor_xy, out);
}